// round 16
// baseline (speedup 1.0000x reference)
#include <cuda_runtime.h>
#include <cuda_fp16.h>
#include <cstdint>

// GraphSAGE 3-layer, mean aggregation — fused layer kernel, MTILE=64, A pure fp16.
// Per layer (one kernel): per block of 64 nodes,
//   warp-gather: agg_i = deg_inv * sum_{j in N(i)} h16[cur]_j  (fp32 accum, fp16 store)
//   MMA: h16[1-cur]_i = act( [agg_i | h16[cur]_i] @ [Wl | Wr]^T + b )
// A fp16 (no lo term); B split fp16 hi+lo (22-bit weights) -> uniform 2-term MMA.
// B packed so each lane's (kb, kb+8) hi/lo fragments form one uint4 (LDG.128).
// 32KB smem/block -> 2 CTAs/SM (gather of one overlaps MMA of the other).

#define NN 100000
#define NE 1600000
#define DD 128
#define SCAN_B 1024
#define NSB 98
#define MTILE 64
#define GRIDM 1563                 // ceil(100000/64)

// ---------------- static device scratch ----------------
__device__ int   g_deg[NN];
__device__ int   g_fill[NN];
__device__ int   g_rowptr[NN];
__device__ float g_deginv[NN];
__device__ int   g_col[NE];
__device__ int   g_bsum[NSB];
__device__ int   g_is64;
__device__ __align__(16) __half g_hA[(size_t)NN * DD];
__device__ __align__(16) __half g_hB[(size_t)NN * DD];
// [layer][n][ks*4+la]: {hi(k0,k0+1), lo(k0,k0+1), hi(k0+8,k0+9), lo(k0+8,k0+9)}, k0=ks*16+la*2
__device__ __align__(16) uint4  g_Bpk[3 * 128 * 64];

// ---------------- helpers ----------------
__device__ __forceinline__ uint32_t smem_u32(const void* p) {
    uint32_t a;
    asm("{ .reg .u64 t; cvta.to.shared.u64 t, %1; cvt.u32.u64 %0, t; }" : "=r"(a) : "l"(p));
    return a;
}
__device__ __forceinline__ void ldmatrix_x4(uint32_t& r0, uint32_t& r1, uint32_t& r2, uint32_t& r3, uint32_t addr) {
    asm volatile("ldmatrix.sync.aligned.m8n8.x4.shared.b16 {%0,%1,%2,%3}, [%4];"
                 : "=r"(r0), "=r"(r1), "=r"(r2), "=r"(r3) : "r"(addr));
}
__device__ __forceinline__ void mma_f16(float* c, const uint32_t* a, const uint32_t* b) {
    asm volatile("mma.sync.aligned.m16n8k16.row.col.f32.f16.f16.f32 "
                 "{%0,%1,%2,%3}, {%4,%5,%6,%7}, {%8,%9}, {%0,%1,%2,%3};"
                 : "+f"(c[0]), "+f"(c[1]), "+f"(c[2]), "+f"(c[3])
                 : "r"(a[0]), "r"(a[1]), "r"(a[2]), "r"(a[3]), "r"(b[0]), "r"(b[1]));
}
__device__ __forceinline__ unsigned short f2h(float f) {
    __half h = __float2half_rn(f);
    return *reinterpret_cast<unsigned short*>(&h);
}
__device__ __forceinline__ float h2f(unsigned short u) {
    __half h = *reinterpret_cast<__half*>(&u);
    return __half2float(h);
}

// ---------------- edge load ----------------
__device__ __forceinline__ int load_edge(const void* ei, int idx, int is64) {
    int v;
    if (is64) v = (int)((const long long*)ei)[idx];
    else      v = ((const int*)ei)[idx];
    v = v < 0 ? 0 : (v >= NN ? NN - 1 : v);
    return v;
}

// ---------------- CSR build ----------------
__global__ void k_zero_detect(const int* __restrict__ ei32) {
    int i = blockIdx.x * blockDim.x + threadIdx.x;
    if (i < NN) { g_deg[i] = 0; g_fill[i] = 0; }
    if (blockIdx.x == 0) {
        __shared__ int nz;
        if (threadIdx.x == 0) nz = 0;
        __syncthreads();
        int local = 0;
        for (int t = threadIdx.x; t < 4096; t += blockDim.x)
            if (ei32[2 * t + 1] != 0) local = 1;
        if (local) atomicOr(&nz, 1);
        __syncthreads();
        if (threadIdx.x == 0) g_is64 = (nz == 0) ? 1 : 0;
    }
}
__global__ void k_hist(const void* __restrict__ ei) {
    int e = blockIdx.x * blockDim.x + threadIdx.x;
    if (e < NE) atomicAdd(&g_deg[load_edge(ei, NE + e, g_is64)], 1);
}
__global__ void k_scan_local() {
    __shared__ int s[2][SCAN_B];
    int t = threadIdx.x, gid = blockIdx.x * SCAN_B + t;
    int v = (gid < NN) ? g_deg[gid] : 0;
    int cur = 0;
    s[0][t] = v;
    __syncthreads();
    for (int off = 1; off < SCAN_B; off <<= 1) {
        int add = (t >= off) ? s[cur][t - off] : 0;
        s[cur ^ 1][t] = s[cur][t] + add;
        cur ^= 1;
        __syncthreads();
    }
    int incl = s[cur][t];
    if (gid < NN) g_rowptr[gid] = incl - v;
    if (t == SCAN_B - 1) g_bsum[blockIdx.x] = incl;
}
__global__ void k_scan_add() {
    __shared__ int sb[NSB];
    __shared__ int pre;
    int t = threadIdx.x;
    if (t < NSB) sb[t] = g_bsum[t];
    __syncthreads();
    if (t == 0) {
        int run = 0;
        for (int b = 0; b < (int)blockIdx.x; b++) run += sb[b];
        pre = run;
    }
    __syncthreads();
    int gid = blockIdx.x * SCAN_B + t;
    if (gid < NN) {
        g_rowptr[gid] += pre;
        int d = g_deg[gid];
        g_deginv[gid] = 1.0f / (float)(d > 1 ? d : 1);
    }
}
__global__ void k_fill(const void* __restrict__ ei) {
    int e = blockIdx.x * blockDim.x + threadIdx.x;
    if (e < NE) {
        int is64 = g_is64;
        int d = load_edge(ei, NE + e, is64);
        int s = load_edge(ei, e, is64);
        int pos = g_rowptr[d] + atomicAdd(&g_fill[d], 1);
        g_col[pos] = s;
    }
}

// ---------------- prep: x -> fp16 buffer A ----------------
__global__ void k_prepA(const float* __restrict__ x) {
    int id = blockIdx.x * blockDim.x + threadIdx.x;      // NN*32
    if (id >= NN * 32) return;
    int row = id >> 5, k4 = id & 31;
    float4 v = __ldg((const float4*)(x + (size_t)row * DD) + k4);
    __half2 a = __floats2half2_rn(v.x, v.y);
    __half2 b = __floats2half2_rn(v.z, v.w);
    uint2 u = make_uint2(*(uint32_t*)&a, *(uint32_t*)&b);
    ((uint2*)g_hA)[(size_t)row * 32 + k4] = u;
}

// ---------------- prep: weights -> packed fp16 hi/lo B (fragment-pair layout) ----------------
__global__ void k_prepW(const float* __restrict__ W1l, const float* __restrict__ W1r,
                        const float* __restrict__ W2l, const float* __restrict__ W2r,
                        const float* __restrict__ W3l, const float* __restrict__ W3r) {
    int id = blockIdx.x * blockDim.x + threadIdx.x;      // 3*128*64
    if (id >= 3 * 128 * 64) return;
    int layer = id / 8192;
    int rem = id & 8191;
    int n = rem >> 6, la4 = rem & 63;
    int ks = la4 >> 2, la = la4 & 3;
    int k0 = ks * 16 + la * 2;                           // k0, k0+1, k0+8, k0+9 same 16-block
    const float* Wl = layer == 0 ? W1l : (layer == 1 ? W2l : W3l);
    const float* Wr = layer == 0 ? W1r : (layer == 1 ? W2r : W3r);
    const float* row = (k0 < 128) ? (Wl + n * DD) : (Wr + (n * DD - 128));
    float2 v01 = __ldg((const float2*)(row + k0));
    float2 v23 = __ldg((const float2*)(row + k0 + 8));
    unsigned short h0 = f2h(v01.x), h1 = f2h(v01.y), h2 = f2h(v23.x), h3 = f2h(v23.y);
    unsigned short l0 = f2h(v01.x - h2f(h0)), l1 = f2h(v01.y - h2f(h1));
    unsigned short l2 = f2h(v23.x - h2f(h2)), l3 = f2h(v23.y - h2f(h3));
    g_Bpk[layer * 8192 + n * 64 + la4] = make_uint4(
        (uint32_t)h0 | ((uint32_t)h1 << 16), (uint32_t)l0 | ((uint32_t)l1 << 16),
        (uint32_t)h2 | ((uint32_t)h3 << 16), (uint32_t)l2 | ((uint32_t)l3 << 16));
}

// ---------------- fused layer: gather + MMA + epilogue (double-buffered h) ----------------
// Block = 64 nodes, 256 threads / 8 warps. wm = wid&1 (32-row group), wn = wid>>1 (32-col group).
__global__ void __launch_bounds__(256, 2) k_fused(
    int layer, int hsel, const float* __restrict__ bias, float* __restrict__ outp, int last)
{
    __shared__ __align__(16) unsigned char sAhi[64 * 512];   // 32 KB (fp16, K=256)

    int tid = threadIdx.x, wid = tid >> 5, lane = tid & 31;
    int rowBase = blockIdx.x * MTILE;
    const __half* hr = (hsel == 0) ? g_hA : g_hB;            // read buffer
    __half*       hw = (hsel == 0) ? g_hB : g_hA;            // write buffer
    const uint2* __restrict__ H = (const uint2*)hr;          // row = 32 uint2 (128 fp16)

    // ---- self half (cols 128..255): exact fp16 copy; 64 rows x 16 uint4, 4 per thread ----
    {
        const uint4* hS = (const uint4*)hr + (size_t)rowBase * 16;
#pragma unroll
        for (int it = 0; it < 4; it++) {
            int idx = it * 256 + tid;
            int r = idx >> 4, u = idx & 15;
            uint4 hv = make_uint4(0u, 0u, 0u, 0u);
            if (rowBase + r < NN) hv = __ldg(&hS[r * 16 + u]);
            int c16 = 16 + u;
            uint32_t off = (uint32_t)(r * 512 + ((c16 ^ (r & 7)) << 4));
            *(uint4*)(sAhi + off) = hv;
        }
    }

    // ---- gather phase: warp wid handles 8 nodes; result stored as fp16 ----
#pragma unroll 1
    for (int s = 0; s < 8; s++) {
        int r = (wid << 3) + s;                  // local row 0..63
        int w = rowBase + r;
        float4 o = make_float4(0.f, 0.f, 0.f, 0.f);
        if (w < NN) {
            int base = __ldg(&g_rowptr[w]);
            int cnt  = __ldg(&g_deg[w]);
            float4 acc = make_float4(0.f, 0.f, 0.f, 0.f);
#define ACC(u) { float2 f0 = __half22float2(*(__half2*)&(u).x); \
                 float2 f1 = __half22float2(*(__half2*)&(u).y); \
                 acc.x += f0.x; acc.y += f0.y; acc.z += f1.x; acc.w += f1.y; }
            int t = 0;
            for (; t + 8 <= cnt; t += 8) {
                int j[8];
#pragma unroll
                for (int q = 0; q < 8; q++) j[q] = __ldg(&g_col[base + t + q]);
                uint2 u[8];
#pragma unroll
                for (int q = 0; q < 8; q++) u[q] = __ldg(&H[(size_t)j[q] * 32 + lane]);
#pragma unroll
                for (int q = 0; q < 8; q++) ACC(u[q])
            }
            if (t + 4 <= cnt) {
                int j[4];
#pragma unroll
                for (int q = 0; q < 4; q++) j[q] = __ldg(&g_col[base + t + q]);
                uint2 u[4];
#pragma unroll
                for (int q = 0; q < 4; q++) u[q] = __ldg(&H[(size_t)j[q] * 32 + lane]);
#pragma unroll
                for (int q = 0; q < 4; q++) ACC(u[q])
                t += 4;
            }
            for (; t < cnt; t++) {
                int j = __ldg(&g_col[base + t]);
                uint2 u = __ldg(&H[(size_t)j * 32 + lane]);
                ACC(u)
            }
#undef ACC
            float di = __ldg(&g_deginv[w]);
            o = make_float4(acc.x * di, acc.y * di, acc.z * di, acc.w * di);
        }
        __half2 p0 = __floats2half2_rn(o.x, o.y);
        __half2 p1 = __floats2half2_rn(o.z, o.w);
        uint2 uh = make_uint2(*(uint32_t*)&p0, *(uint32_t*)&p1);
        int c16 = lane >> 1, half = lane & 1;
        uint32_t sw = (uint32_t)((c16 ^ (r & 7)) << 4) + half * 8;
        *(uint2*)(sAhi + r * 512 + sw) = uh;
    }
    __syncthreads();

    // ---- MMA phase: uniform 2 terms (Ah*Bh + Ah*Bl) for all 16 k-steps ----
    uint32_t aHiBase = smem_u32(sAhi);
    int wm = wid & 1, wn = wid >> 1;
    const uint4* __restrict__ Bpk = g_Bpk + (size_t)layer * 8192;

    float acc[2][4][4];
#pragma unroll
    for (int mt = 0; mt < 2; mt++)
#pragma unroll
        for (int nt = 0; nt < 4; nt++)
#pragma unroll
            for (int q = 0; q < 4; q++) acc[mt][nt][q] = 0.0f;

#pragma unroll
    for (int ks = 0; ks < 16; ks++) {
        uint32_t ah[2][4];
#pragma unroll
        for (int mt = 0; mt < 2; mt++) {
            int r = wm * 32 + mt * 16 + (lane & 15);
            int c16 = ks * 2 + (lane >> 4);
            uint32_t sw = (uint32_t)((c16 ^ (r & 7)) << 4);
            ldmatrix_x4(ah[mt][0], ah[mt][1], ah[mt][2], ah[mt][3], aHiBase + r * 512 + sw);
        }
        uint32_t bh[4][2], bl[4][2];
#pragma unroll
        for (int nt = 0; nt < 4; nt++) {
            int n = wn * 32 + nt * 8 + (lane >> 2);
            uint4 p = __ldg(&Bpk[n * 64 + ks * 4 + (lane & 3)]);
            bh[nt][0] = p.x; bh[nt][1] = p.z;
            bl[nt][0] = p.y; bl[nt][1] = p.w;
        }
#pragma unroll
        for (int nt = 0; nt < 4; nt++)
#pragma unroll
            for (int mt = 0; mt < 2; mt++) {
                mma_f16(acc[mt][nt], ah[mt], bh[nt]);
                mma_f16(acc[mt][nt], ah[mt], bl[nt]);
            }
    }

    // ---- epilogue: +bias (direct ldg), (ReLU), write h16 / fp32 out ----
#pragma unroll
    for (int mt = 0; mt < 2; mt++) {
        int r0 = rowBase + wm * 32 + mt * 16 + (lane >> 2);
#pragma unroll
        for (int nt = 0; nt < 4; nt++) {
            int col = wn * 32 + nt * 8 + (lane & 3) * 2;
            float2 b = __ldg((const float2*)(bias + col));
            float2 v01 = make_float2(acc[mt][nt][0] + b.x, acc[mt][nt][1] + b.y);
            float2 v23 = make_float2(acc[mt][nt][2] + b.x, acc[mt][nt][3] + b.y);
            if (!last) {
                v01.x = fmaxf(v01.x, 0.f); v01.y = fmaxf(v01.y, 0.f);
                v23.x = fmaxf(v23.x, 0.f); v23.y = fmaxf(v23.y, 0.f);
            }
            if (last) {
                if (r0 < NN)     *(float2*)(outp + (size_t)r0 * DD + col)       = v01;
                if (r0 + 8 < NN) *(float2*)(outp + (size_t)(r0 + 8) * DD + col) = v23;
            } else {
                if (r0 < NN) {
                    __half2 hh = __floats2half2_rn(v01.x, v01.y);
                    *(__half2*)(hw + (size_t)r0 * DD + col) = hh;
                }
                if (r0 + 8 < NN) {
                    __half2 hh = __floats2half2_rn(v23.x, v23.y);
                    *(__half2*)(hw + (size_t)(r0 + 8) * DD + col) = hh;
                }
            }
        }
    }
}

// ---------------- launch ----------------
extern "C" void kernel_launch(void* const* d_in, const int* in_sizes, int n_in,
                              void* d_out, int out_size)
{
    const float* x  = nullptr;
    const void*  ei = nullptr;
    const float* Wm[6] = {nullptr, nullptr, nullptr, nullptr, nullptr, nullptr};
    const float* Bm[3] = {nullptr, nullptr, nullptr};
    int nw = 0, nb = 0;
    for (int i = 0; i < n_in; i++) {
        long long sz = in_sizes[i];
        if (sz == (long long)NN * DD)      x  = (const float*)d_in[i];
        else if (sz == (long long)2 * NE)  ei = d_in[i];
        else if (sz == (long long)NE)      { /* edge_attr, unused */ }
        else if (sz == DD * DD)            { if (nw < 6) Wm[nw++] = (const float*)d_in[i]; }
        else if (sz == DD)                 { if (nb < 3) Bm[nb++] = (const float*)d_in[i]; }
    }
    float* out = (float*)d_out;
    if (!x || !ei || nw < 6 || nb < 3) return;

    const int EB = (NE + 255) / 256;
    const int NB = (NN + 255) / 256;
    const int PA = (NN * 32 + 255) / 256;
    const int PW = (3 * 128 * 64 + 255) / 256;

    // CSR build
    k_zero_detect<<<NB, 256>>>((const int*)ei);
    k_hist<<<EB, 256>>>(ei);
    k_scan_local<<<NSB, SCAN_B>>>();
    k_scan_add<<<NSB, SCAN_B>>>();
    k_fill<<<EB, 256>>>(ei);

    // prep
    k_prepA<<<PA, 256>>>(x);
    k_prepW<<<PW, 256>>>(Wm[0], Wm[1], Wm[2], Wm[3], Wm[4], Wm[5]);

    // fused layers (double-buffered: A->B, B->A, A->out)
    k_fused<<<GRIDM, 256>>>(0, 0, Bm[0], nullptr, 0);
    k_fused<<<GRIDM, 256>>>(1, 1, Bm[1], nullptr, 0);
    k_fused<<<GRIDM, 256>>>(2, 0, Bm[2], out, 1);
}

// round 17
// speedup vs baseline: 1.1632x; 1.1632x over previous
#include <cuda_runtime.h>
#include <cuda_fp16.h>
#include <cstdint>

// GraphSAGE 3-layer, mean aggregation — fused layer kernel, MTILE=64, A pure fp16.
// Per layer (one kernel): per block of 64 nodes,
//   warp-gather: agg_i = deg_inv * sum_{j in N(i)} h16[cur]_j  (fp32 accum, fp16 store)
//   MMA: h16[1-cur]_i = act( [agg_i | h16[cur]_i] @ [Wl | Wr]^T + b )
// A fp16 (no lo term); B split fp16 hi+lo (22-bit weights) -> uniform 2-term MMA.
// B packed so each lane's (kb, kb+8) hi/lo fragments form one uint4 (LDG.128).
// NO occupancy cap: ptxas free register allocation (R16's (256,2) cap caused spills).

#define NN 100000
#define NE 1600000
#define DD 128
#define SCAN_B 1024
#define NSB 98
#define MTILE 64
#define GRIDM 1563                 // ceil(100000/64)

// ---------------- static device scratch ----------------
__device__ int   g_deg[NN];
__device__ int   g_fill[NN];
__device__ int   g_rowptr[NN];
__device__ float g_deginv[NN];
__device__ int   g_col[NE];
__device__ int   g_bsum[NSB];
__device__ int   g_is64;
__device__ __align__(16) __half g_hA[(size_t)NN * DD];
__device__ __align__(16) __half g_hB[(size_t)NN * DD];
// [layer][n][ks*4+la]: {hi(k0,k0+1), lo(k0,k0+1), hi(k0+8,k0+9), lo(k0+8,k0+9)}, k0=ks*16+la*2
__device__ __align__(16) uint4  g_Bpk[3 * 128 * 64];

// ---------------- helpers ----------------
__device__ __forceinline__ uint32_t smem_u32(const void* p) {
    uint32_t a;
    asm("{ .reg .u64 t; cvta.to.shared.u64 t, %1; cvt.u32.u64 %0, t; }" : "=r"(a) : "l"(p));
    return a;
}
__device__ __forceinline__ void ldmatrix_x4(uint32_t& r0, uint32_t& r1, uint32_t& r2, uint32_t& r3, uint32_t addr) {
    asm volatile("ldmatrix.sync.aligned.m8n8.x4.shared.b16 {%0,%1,%2,%3}, [%4];"
                 : "=r"(r0), "=r"(r1), "=r"(r2), "=r"(r3) : "r"(addr));
}
__device__ __forceinline__ void mma_f16(float* c, const uint32_t* a, const uint32_t* b) {
    asm volatile("mma.sync.aligned.m16n8k16.row.col.f32.f16.f16.f32 "
                 "{%0,%1,%2,%3}, {%4,%5,%6,%7}, {%8,%9}, {%0,%1,%2,%3};"
                 : "+f"(c[0]), "+f"(c[1]), "+f"(c[2]), "+f"(c[3])
                 : "r"(a[0]), "r"(a[1]), "r"(a[2]), "r"(a[3]), "r"(b[0]), "r"(b[1]));
}
__device__ __forceinline__ unsigned short f2h(float f) {
    __half h = __float2half_rn(f);
    return *reinterpret_cast<unsigned short*>(&h);
}
__device__ __forceinline__ float h2f(unsigned short u) {
    __half h = *reinterpret_cast<__half*>(&u);
    return __half2float(h);
}

// ---------------- edge load ----------------
__device__ __forceinline__ int load_edge(const void* ei, int idx, int is64) {
    int v;
    if (is64) v = (int)((const long long*)ei)[idx];
    else      v = ((const int*)ei)[idx];
    v = v < 0 ? 0 : (v >= NN ? NN - 1 : v);
    return v;
}

// ---------------- CSR build ----------------
__global__ void k_zero_detect(const int* __restrict__ ei32) {
    int i = blockIdx.x * blockDim.x + threadIdx.x;
    if (i < NN) { g_deg[i] = 0; g_fill[i] = 0; }
    if (blockIdx.x == 0) {
        __shared__ int nz;
        if (threadIdx.x == 0) nz = 0;
        __syncthreads();
        int local = 0;
        for (int t = threadIdx.x; t < 4096; t += blockDim.x)
            if (ei32[2 * t + 1] != 0) local = 1;
        if (local) atomicOr(&nz, 1);
        __syncthreads();
        if (threadIdx.x == 0) g_is64 = (nz == 0) ? 1 : 0;
    }
}
__global__ void k_hist(const void* __restrict__ ei) {
    int e = blockIdx.x * blockDim.x + threadIdx.x;
    if (e < NE) atomicAdd(&g_deg[load_edge(ei, NE + e, g_is64)], 1);
}
__global__ void k_scan_local() {
    __shared__ int s[2][SCAN_B];
    int t = threadIdx.x, gid = blockIdx.x * SCAN_B + t;
    int v = (gid < NN) ? g_deg[gid] : 0;
    int cur = 0;
    s[0][t] = v;
    __syncthreads();
    for (int off = 1; off < SCAN_B; off <<= 1) {
        int add = (t >= off) ? s[cur][t - off] : 0;
        s[cur ^ 1][t] = s[cur][t] + add;
        cur ^= 1;
        __syncthreads();
    }
    int incl = s[cur][t];
    if (gid < NN) g_rowptr[gid] = incl - v;
    if (t == SCAN_B - 1) g_bsum[blockIdx.x] = incl;
}
__global__ void k_scan_add() {
    __shared__ int sb[NSB];
    __shared__ int pre;
    int t = threadIdx.x;
    if (t < NSB) sb[t] = g_bsum[t];
    __syncthreads();
    if (t == 0) {
        int run = 0;
        for (int b = 0; b < (int)blockIdx.x; b++) run += sb[b];
        pre = run;
    }
    __syncthreads();
    int gid = blockIdx.x * SCAN_B + t;
    if (gid < NN) {
        g_rowptr[gid] += pre;
        int d = g_deg[gid];
        g_deginv[gid] = 1.0f / (float)(d > 1 ? d : 1);
    }
}
__global__ void k_fill(const void* __restrict__ ei) {
    int e = blockIdx.x * blockDim.x + threadIdx.x;
    if (e < NE) {
        int is64 = g_is64;
        int d = load_edge(ei, NE + e, is64);
        int s = load_edge(ei, e, is64);
        int pos = g_rowptr[d] + atomicAdd(&g_fill[d], 1);
        g_col[pos] = s;
    }
}

// ---------------- prep: x -> fp16 buffer A ----------------
__global__ void k_prepA(const float* __restrict__ x) {
    int id = blockIdx.x * blockDim.x + threadIdx.x;      // NN*32
    if (id >= NN * 32) return;
    int row = id >> 5, k4 = id & 31;
    float4 v = __ldg((const float4*)(x + (size_t)row * DD) + k4);
    __half2 a = __floats2half2_rn(v.x, v.y);
    __half2 b = __floats2half2_rn(v.z, v.w);
    uint2 u = make_uint2(*(uint32_t*)&a, *(uint32_t*)&b);
    ((uint2*)g_hA)[(size_t)row * 32 + k4] = u;
}

// ---------------- prep: weights -> packed fp16 hi/lo B (fragment-pair layout) ----------------
__global__ void k_prepW(const float* __restrict__ W1l, const float* __restrict__ W1r,
                        const float* __restrict__ W2l, const float* __restrict__ W2r,
                        const float* __restrict__ W3l, const float* __restrict__ W3r) {
    int id = blockIdx.x * blockDim.x + threadIdx.x;      // 3*128*64
    if (id >= 3 * 128 * 64) return;
    int layer = id / 8192;
    int rem = id & 8191;
    int n = rem >> 6, la4 = rem & 63;
    int ks = la4 >> 2, la = la4 & 3;
    int k0 = ks * 16 + la * 2;                           // k0, k0+1, k0+8, k0+9 same 16-block
    const float* Wl = layer == 0 ? W1l : (layer == 1 ? W2l : W3l);
    const float* Wr = layer == 0 ? W1r : (layer == 1 ? W2r : W3r);
    const float* row = (k0 < 128) ? (Wl + n * DD) : (Wr + (n * DD - 128));
    float2 v01 = __ldg((const float2*)(row + k0));
    float2 v23 = __ldg((const float2*)(row + k0 + 8));
    unsigned short h0 = f2h(v01.x), h1 = f2h(v01.y), h2 = f2h(v23.x), h3 = f2h(v23.y);
    unsigned short l0 = f2h(v01.x - h2f(h0)), l1 = f2h(v01.y - h2f(h1));
    unsigned short l2 = f2h(v23.x - h2f(h2)), l3 = f2h(v23.y - h2f(h3));
    g_Bpk[layer * 8192 + n * 64 + la4] = make_uint4(
        (uint32_t)h0 | ((uint32_t)h1 << 16), (uint32_t)l0 | ((uint32_t)l1 << 16),
        (uint32_t)h2 | ((uint32_t)h3 << 16), (uint32_t)l2 | ((uint32_t)l3 << 16));
}

// ---------------- fused layer: gather + MMA + epilogue (double-buffered h) ----------------
// Block = 64 nodes, 256 threads / 8 warps. wm = wid&1 (32-row group), wn = wid>>1 (32-col group).
__global__ void __launch_bounds__(256) k_fused(
    int layer, int hsel, const float* __restrict__ bias, float* __restrict__ outp, int last)
{
    __shared__ __align__(16) unsigned char sAhi[64 * 512];   // 32 KB (fp16, K=256)

    int tid = threadIdx.x, wid = tid >> 5, lane = tid & 31;
    int rowBase = blockIdx.x * MTILE;
    const __half* hr = (hsel == 0) ? g_hA : g_hB;            // read buffer
    __half*       hw = (hsel == 0) ? g_hB : g_hA;            // write buffer
    const uint2* __restrict__ H = (const uint2*)hr;          // row = 32 uint2 (128 fp16)

    // ---- self half (cols 128..255): exact fp16 copy; 64 rows x 16 uint4, 4 per thread ----
    {
        const uint4* hS = (const uint4*)hr + (size_t)rowBase * 16;
#pragma unroll
        for (int it = 0; it < 4; it++) {
            int idx = it * 256 + tid;
            int r = idx >> 4, u = idx & 15;
            uint4 hv = make_uint4(0u, 0u, 0u, 0u);
            if (rowBase + r < NN) hv = __ldg(&hS[r * 16 + u]);
            int c16 = 16 + u;
            uint32_t off = (uint32_t)(r * 512 + ((c16 ^ (r & 7)) << 4));
            *(uint4*)(sAhi + off) = hv;
        }
    }

    // ---- gather phase: warp wid handles 8 nodes; result stored as fp16 ----
#pragma unroll 1
    for (int s = 0; s < 8; s++) {
        int r = (wid << 3) + s;                  // local row 0..63
        int w = rowBase + r;
        float4 o = make_float4(0.f, 0.f, 0.f, 0.f);
        if (w < NN) {
            int base = __ldg(&g_rowptr[w]);
            int cnt  = __ldg(&g_deg[w]);
            float4 acc = make_float4(0.f, 0.f, 0.f, 0.f);
#define ACC(u) { float2 f0 = __half22float2(*(__half2*)&(u).x); \
                 float2 f1 = __half22float2(*(__half2*)&(u).y); \
                 acc.x += f0.x; acc.y += f0.y; acc.z += f1.x; acc.w += f1.y; }
            int t = 0;
            for (; t + 8 <= cnt; t += 8) {
                int j[8];
#pragma unroll
                for (int q = 0; q < 8; q++) j[q] = __ldg(&g_col[base + t + q]);
                uint2 u[8];
#pragma unroll
                for (int q = 0; q < 8; q++) u[q] = __ldg(&H[(size_t)j[q] * 32 + lane]);
#pragma unroll
                for (int q = 0; q < 8; q++) ACC(u[q])
            }
            if (t + 4 <= cnt) {
                int j[4];
#pragma unroll
                for (int q = 0; q < 4; q++) j[q] = __ldg(&g_col[base + t + q]);
                uint2 u[4];
#pragma unroll
                for (int q = 0; q < 4; q++) u[q] = __ldg(&H[(size_t)j[q] * 32 + lane]);
#pragma unroll
                for (int q = 0; q < 4; q++) ACC(u[q])
                t += 4;
            }
            for (; t < cnt; t++) {
                int j = __ldg(&g_col[base + t]);
                uint2 u = __ldg(&H[(size_t)j * 32 + lane]);
                ACC(u)
            }
#undef ACC
            float di = __ldg(&g_deginv[w]);
            o = make_float4(acc.x * di, acc.y * di, acc.z * di, acc.w * di);
        }
        __half2 p0 = __floats2half2_rn(o.x, o.y);
        __half2 p1 = __floats2half2_rn(o.z, o.w);
        uint2 uh = make_uint2(*(uint32_t*)&p0, *(uint32_t*)&p1);
        int c16 = lane >> 1, half = lane & 1;
        uint32_t sw = (uint32_t)((c16 ^ (r & 7)) << 4) + half * 8;
        *(uint2*)(sAhi + r * 512 + sw) = uh;
    }
    __syncthreads();

    // ---- MMA phase: uniform 2 terms (Ah*Bh + Ah*Bl) for all 16 k-steps ----
    uint32_t aHiBase = smem_u32(sAhi);
    int wm = wid & 1, wn = wid >> 1;
    const uint4* __restrict__ Bpk = g_Bpk + (size_t)layer * 8192;

    float acc[2][4][4];
#pragma unroll
    for (int mt = 0; mt < 2; mt++)
#pragma unroll
        for (int nt = 0; nt < 4; nt++)
#pragma unroll
            for (int q = 0; q < 4; q++) acc[mt][nt][q] = 0.0f;

#pragma unroll
    for (int ks = 0; ks < 16; ks++) {
        uint32_t ah[2][4];
#pragma unroll
        for (int mt = 0; mt < 2; mt++) {
            int r = wm * 32 + mt * 16 + (lane & 15);
            int c16 = ks * 2 + (lane >> 4);
            uint32_t sw = (uint32_t)((c16 ^ (r & 7)) << 4);
            ldmatrix_x4(ah[mt][0], ah[mt][1], ah[mt][2], ah[mt][3], aHiBase + r * 512 + sw);
        }
        uint32_t bh[4][2], bl[4][2];
#pragma unroll
        for (int nt = 0; nt < 4; nt++) {
            int n = wn * 32 + nt * 8 + (lane >> 2);
            uint4 p = __ldg(&Bpk[n * 64 + ks * 4 + (lane & 3)]);
            bh[nt][0] = p.x; bh[nt][1] = p.z;
            bl[nt][0] = p.y; bl[nt][1] = p.w;
        }
#pragma unroll
        for (int nt = 0; nt < 4; nt++)
#pragma unroll
            for (int mt = 0; mt < 2; mt++) {
                mma_f16(acc[mt][nt], ah[mt], bh[nt]);
                mma_f16(acc[mt][nt], ah[mt], bl[nt]);
            }
    }

    // ---- epilogue: +bias (direct ldg), (ReLU), write h16 / fp32 out ----
#pragma unroll
    for (int mt = 0; mt < 2; mt++) {
        int r0 = rowBase + wm * 32 + mt * 16 + (lane >> 2);
#pragma unroll
        for (int nt = 0; nt < 4; nt++) {
            int col = wn * 32 + nt * 8 + (lane & 3) * 2;
            float2 b = __ldg((const float2*)(bias + col));
            float2 v01 = make_float2(acc[mt][nt][0] + b.x, acc[mt][nt][1] + b.y);
            float2 v23 = make_float2(acc[mt][nt][2] + b.x, acc[mt][nt][3] + b.y);
            if (!last) {
                v01.x = fmaxf(v01.x, 0.f); v01.y = fmaxf(v01.y, 0.f);
                v23.x = fmaxf(v23.x, 0.f); v23.y = fmaxf(v23.y, 0.f);
            }
            if (last) {
                if (r0 < NN)     *(float2*)(outp + (size_t)r0 * DD + col)       = v01;
                if (r0 + 8 < NN) *(float2*)(outp + (size_t)(r0 + 8) * DD + col) = v23;
            } else {
                if (r0 < NN) {
                    __half2 hh = __floats2half2_rn(v01.x, v01.y);
                    *(__half2*)(hw + (size_t)r0 * DD + col) = hh;
                }
                if (r0 + 8 < NN) {
                    __half2 hh = __floats2half2_rn(v23.x, v23.y);
                    *(__half2*)(hw + (size_t)(r0 + 8) * DD + col) = hh;
                }
            }
        }
    }
}

// ---------------- launch ----------------
extern "C" void kernel_launch(void* const* d_in, const int* in_sizes, int n_in,
                              void* d_out, int out_size)
{
    const float* x  = nullptr;
    const void*  ei = nullptr;
    const float* Wm[6] = {nullptr, nullptr, nullptr, nullptr, nullptr, nullptr};
    const float* Bm[3] = {nullptr, nullptr, nullptr};
    int nw = 0, nb = 0;
    for (int i = 0; i < n_in; i++) {
        long long sz = in_sizes[i];
        if (sz == (long long)NN * DD)      x  = (const float*)d_in[i];
        else if (sz == (long long)2 * NE)  ei = d_in[i];
        else if (sz == (long long)NE)      { /* edge_attr, unused */ }
        else if (sz == DD * DD)            { if (nw < 6) Wm[nw++] = (const float*)d_in[i]; }
        else if (sz == DD)                 { if (nb < 3) Bm[nb++] = (const float*)d_in[i]; }
    }
    float* out = (float*)d_out;
    if (!x || !ei || nw < 6 || nb < 3) return;

    const int EB = (NE + 255) / 256;
    const int NB = (NN + 255) / 256;
    const int PA = (NN * 32 + 255) / 256;
    const int PW = (3 * 128 * 64 + 255) / 256;

    // CSR build
    k_zero_detect<<<NB, 256>>>((const int*)ei);
    k_hist<<<EB, 256>>>(ei);
    k_scan_local<<<NSB, SCAN_B>>>();
    k_scan_add<<<NSB, SCAN_B>>>();
    k_fill<<<EB, 256>>>(ei);

    // prep
    k_prepA<<<PA, 256>>>(x);
    k_prepW<<<PW, 256>>>(Wm[0], Wm[1], Wm[2], Wm[3], Wm[4], Wm[5]);

    // fused layers (double-buffered: A->B, B->A, A->out)
    k_fused<<<GRIDM, 256>>>(0, 0, Bm[0], nullptr, 0);
    k_fused<<<GRIDM, 256>>>(1, 1, Bm[1], nullptr, 0);
    k_fused<<<GRIDM, 256>>>(2, 0, Bm[2], out, 1);
}